// round 15
// baseline (speedup 1.0000x reference)
#include <cuda_runtime.h>
#include <cuda_fp16.h>
#include <math.h>
#include <stdint.h>

#define D_MODEL 1024
#define N_HEAD  16
#define T_LEN   512
#define S_LEN   1024
#define BATCH   16
#define MQ      (T_LEN * BATCH)   /* 8192  query rows  */
#define MKV     (S_LEN * BATCH)   /* 16384 kv rows     */

// ---------------- scratch (static device globals; no allocation) ------------
#define WS_SA_IN  0u
#define WS_SA_OUT (3u*1024*1024)
#define WS_CA_IN  (4u*1024*1024)
#define WS_CA_OUT (7u*1024*1024)
#define WS_FC     (8u*1024*1024)
#define WS_PROJ   (12u*1024*1024)
#define WS_TOTAL  (16u*1024*1024)
__device__ __half g_w  [WS_TOTAL];            // fp16 weights
__device__ __half g_hid[MKV * D_MODEL];       // fp16 hidden_states
__device__ __half g_h  [MQ * D_MODEL];        // LN output
__device__ __half g_qkv[MQ * 3 * D_MODEL];
__device__ __half g_kv [MKV * 2 * D_MODEL];
__device__ __half g_ctx[MQ * D_MODEL];
__device__ __half g_ffn[MQ * 4 * D_MODEL];

__device__ __forceinline__ uint32_t h2u(__half2 x) {
    return *reinterpret_cast<uint32_t*>(&x);
}
__device__ __forceinline__ uint32_t smem_u32(const void* p) {
    uint32_t a;
    asm("{ .reg .u64 t; cvta.to.shared.u64 t, %1; cvt.u32.u64 %0, t; }"
        : "=r"(a) : "l"(p));
    return a;
}
__device__ __forceinline__ void cp_async16(uint32_t s, const void* g) {
    asm volatile("cp.async.cg.shared.global [%0], [%1], 16;" :: "r"(s), "l"(g));
}
__device__ __forceinline__ void cp_commit() {
    asm volatile("cp.async.commit_group;");
}
__device__ __forceinline__ void cp_wait1() {
    asm volatile("cp.async.wait_group 1;");
}
__device__ __forceinline__ void ldsm4(uint32_t* r, uint32_t addr) {
    asm volatile("ldmatrix.sync.aligned.m8n8.x4.shared.b16 {%0,%1,%2,%3}, [%4];"
                 : "=r"(r[0]), "=r"(r[1]), "=r"(r[2]), "=r"(r[3]) : "r"(addr));
}
__device__ __forceinline__ void ldsm4t(uint32_t* r, uint32_t addr) {
    asm volatile("ldmatrix.sync.aligned.m8n8.x4.trans.shared.b16 {%0,%1,%2,%3}, [%4];"
                 : "=r"(r[0]), "=r"(r[1]), "=r"(r[2]), "=r"(r[3]) : "r"(addr));
}
__device__ __forceinline__ void mma_fp16(float* c, const uint32_t* a,
                                         const uint32_t* b) {
    asm volatile(
        "mma.sync.aligned.m16n8k16.row.col.f32.f16.f16.f32 "
        "{%0,%1,%2,%3}, {%4,%5,%6,%7}, {%8,%9}, {%0,%1,%2,%3};"
        : "+f"(c[0]), "+f"(c[1]), "+f"(c[2]), "+f"(c[3])
        : "r"(a[0]), "r"(a[1]), "r"(a[2]), "r"(a[3]),
          "r"(b[0]), "r"(b[1]));
}

// ======================= FP16 single-pass GEMM ==============================
// Tile 256x128, BK=64 (128B rows, SW128 swizzle), 3-stage cp.async (144KB),
// 1 CTA/SM, 8 warps 4x2 (warp: 64 rows x 64 cols), single sync/iteration:
// wait (chunk c) -> sync -> issue c+2 -> compute c.
#define GEMM_STAGE 49152           /* A 32KB + B 16KB */
#define GEMM_SMEM  (3 * GEMM_STAGE)
__global__ __launch_bounds__(256, 1) void gemm_fp16(
    const __half* __restrict__ A, int lda,
    const __half* __restrict__ B, int ldb,
    const float* __restrict__ bias,
    const float* __restrict__ res,
    float* __restrict__ Cf, __half* __restrict__ Ch,
    int ldc, int K, int act)
{
    extern __shared__ char dsm[];
    const uint32_t smem_base = smem_u32(dsm);
    const int tid = threadIdx.x, wid = tid >> 5, lane = tid & 31;
    const int wm = wid >> 1, wn = wid & 1;
    const int m0 = blockIdx.y * 256, n0 = blockIdx.x * 128;

    float acc[4][8][4];
    #pragma unroll
    for (int i = 0; i < 4; i++)
        #pragma unroll
        for (int j = 0; j < 8; j++)
            #pragma unroll
            for (int q = 0; q < 4; q++) acc[i][j][q] = 0.f;

    const int nCh = K >> 6;
    auto issue = [&](int c) {
        const int k0 = c << 6;
        const uint32_t sb = smem_base + (c % 3) * GEMM_STAGE;
        #pragma unroll
        for (int it = 0; it < 8; it++) {                 // A: 256 rows
            int idx = tid + (it << 8);
            int r = idx >> 3, q = idx & 7;
            uint32_t so = sb + r * 128 + ((q ^ (r & 7)) << 4);
            cp_async16(so, A + (size_t)(m0 + r) * lda + k0 + q * 8);
        }
        #pragma unroll
        for (int it = 0; it < 4; it++) {                 // B: 128 rows
            int idx = tid + (it << 8);
            int n = idx >> 3, q = idx & 7;
            uint32_t so = sb + 32768 + n * 128 + ((q ^ (n & 7)) << 4);
            cp_async16(so, B + (size_t)(n0 + n) * ldb + k0 + q * 8);
        }
    };

    issue(0); cp_commit();
    issue(1); cp_commit();

    for (int c = 0; c < nCh; c++) {
        cp_wait1();
        __syncthreads();
        if (c + 2 < nCh) issue(c + 2);
        cp_commit();
        const uint32_t sb = smem_base + (c % 3) * GEMM_STAGE;
        #pragma unroll
        for (int ks = 0; ks < 4; ks++) {
            uint32_t a[4][4];
            #pragma unroll
            for (int mt = 0; mt < 4; mt++) {
                int row = wm * 64 + mt * 16 + (lane & 15);
                int cc  = 2 * ks + (lane >> 4);
                ldsm4(a[mt], sb + row * 128 + ((cc ^ (row & 7)) << 4));
            }
            #pragma unroll
            for (int ntp = 0; ntp < 4; ntp++) {
                int nrow = wn * 64 + ntp * 16 + (lane & 7)
                         + ((lane & 16) ? 8 : 0);
                int cc   = 2 * ks + ((lane >> 3) & 1);
                uint32_t b[4];
                ldsm4(b, sb + 32768 + nrow * 128 + ((cc ^ (nrow & 7)) << 4));
                #pragma unroll
                for (int half = 0; half < 2; half++) {
                    int nt = ntp * 2 + half;
                    #pragma unroll
                    for (int mt = 0; mt < 4; mt++)
                        mma_fp16(acc[mt][nt], a[mt], b + half * 2);
                }
            }
        }
    }

    const int r0 = m0 + wm * 64 + (lane >> 2);
    const int c0 = n0 + wn * 64 + (lane & 3) * 2;
    #pragma unroll
    for (int mt = 0; mt < 4; mt++) {
        #pragma unroll
        for (int nt = 0; nt < 8; nt++) {
            int col = c0 + nt * 8;
            float2 bv = make_float2(0.f, 0.f);
            if (bias) bv = *(const float2*)(bias + col);
            #pragma unroll
            for (int hrow = 0; hrow < 2; hrow++) {
                int row = r0 + mt * 16 + hrow * 8;
                float2 vv;
                vv.x = acc[mt][nt][hrow * 2 + 0] + bv.x;
                vv.y = acc[mt][nt][hrow * 2 + 1] + bv.y;
                size_t co = (size_t)row * ldc + col;
                if (res) {
                    float2 rr = *(const float2*)(res + co);
                    vv.x += rr.x; vv.y += rr.y;
                }
                if (act) {
                    vv.x = vv.x / (1.f + __expf(-1.702f * vv.x));
                    vv.y = vv.y / (1.f + __expf(-1.702f * vv.y));
                }
                if (Cf) {
                    *(float2*)(Cf + co) = vv;
                } else {
                    *(uint32_t*)(Ch + co) = h2u(__floats2half2_rn(vv.x, vv.y));
                }
            }
        }
    }
}

// ======================= flash attention (fp16, 3-stage, 1 sync/iter) =======
// Grid (1, T/128, 256). smem: Q 16KB + 3 KV stages x 16KB = 64KB.
#define FLASH_SMEM (16384 + 3 * 16384)
__global__ __launch_bounds__(256) void flash_kernel(
    const __half* __restrict__ Q, int ldq,
    const __half* __restrict__ K, int ldk,
    const __half* __restrict__ V, int ldv,
    __half* __restrict__ O, int S)
{
    extern __shared__ char dsm[];
    const uint32_t sQ  = smem_u32(dsm);
    const uint32_t sKV = sQ + 16384;
    const int tid = threadIdx.x, wid = tid >> 5, lane = tid & 31;
    const int z = blockIdx.z, b = z & 15, h = z >> 4;
    const int t0 = blockIdx.y * 128;
    const int hcol = h * 64;

    #pragma unroll
    for (int p = 0; p < 4; p++) {
        int idx = tid + (p << 8);
        int r = idx >> 3, q = idx & 7;
        uint32_t so = sQ + r * 128 + ((q ^ (r & 7)) << 4);
        cp_async16(so, Q + (size_t)((t0 + r) * BATCH + b) * ldq + hcol + q * 8);
    }
    auto issue_kv = [&](int c) {
        int s0 = c << 6;
        uint32_t sb = sKV + (c % 3) * 16384;
        #pragma unroll
        for (int p = 0; p < 2; p++) {
            int idx = tid + (p << 8);
            int r = idx >> 3, q = idx & 7;
            uint32_t so = sb + r * 128 + ((q ^ (r & 7)) << 4);
            size_t rowg = (size_t)((s0 + r) * BATCH + b);
            cp_async16(so,        K + rowg * ldk + hcol + q * 8);
            cp_async16(so + 8192, V + rowg * ldv + hcol + q * 8);
        }
    };
    issue_kv(0); cp_commit();
    issue_kv(1); cp_commit();

    float out[8][4];
    #pragma unroll
    for (int i = 0; i < 8; i++)
        #pragma unroll
        for (int j = 0; j < 4; j++) out[i][j] = 0.f;
    float mrow0 = -1e30f, mrow1 = -1e30f, lrow0 = 0.f, lrow1 = 0.f;

    const int nCh = S >> 6;
    for (int c = 0; c < nCh; c++) {
        cp_wait1();
        __syncthreads();
        const uint32_t sb = sKV + (c % 3) * 16384;

        // ---- scores ----
        float sc[8][4];
        #pragma unroll
        for (int i = 0; i < 8; i++)
            #pragma unroll
            for (int j = 0; j < 4; j++) sc[i][j] = 0.f;
        #pragma unroll
        for (int ks = 0; ks < 4; ks++) {
            uint32_t a[4];
            {
                int row = wid * 16 + (lane & 15);
                int cc  = 2 * ks + (lane >> 4);
                ldsm4(a, sQ + row * 128 + ((cc ^ (row & 7)) << 4));
            }
            #pragma unroll
            for (int ntp = 0; ntp < 4; ntp++) {
                int nrow = ntp * 16 + (lane & 7) + ((lane & 16) ? 8 : 0);
                int cc   = 2 * ks + ((lane >> 3) & 1);
                uint32_t bq[4];
                ldsm4(bq, sb + nrow * 128 + ((cc ^ (nrow & 7)) << 4));
                mma_fp16(sc[ntp * 2 + 0], a, bq);
                mma_fp16(sc[ntp * 2 + 1], a, bq + 2);
            }
        }

        // ---- online softmax ----
        float mx0 = -1e30f, mx1 = -1e30f;
        #pragma unroll
        for (int nt = 0; nt < 8; nt++) {
            sc[nt][0] *= 0.125f; sc[nt][1] *= 0.125f;
            sc[nt][2] *= 0.125f; sc[nt][3] *= 0.125f;
            mx0 = fmaxf(mx0, fmaxf(sc[nt][0], sc[nt][1]));
            mx1 = fmaxf(mx1, fmaxf(sc[nt][2], sc[nt][3]));
        }
        mx0 = fmaxf(mx0, __shfl_xor_sync(~0u, mx0, 1));
        mx0 = fmaxf(mx0, __shfl_xor_sync(~0u, mx0, 2));
        mx1 = fmaxf(mx1, __shfl_xor_sync(~0u, mx1, 1));
        mx1 = fmaxf(mx1, __shfl_xor_sync(~0u, mx1, 2));
        float mn0 = fmaxf(mrow0, mx0), mn1 = fmaxf(mrow1, mx1);
        float cf0 = __expf(mrow0 - mn0), cf1 = __expf(mrow1 - mn1);
        mrow0 = mn0; mrow1 = mn1;
        float sum0 = 0.f, sum1 = 0.f;
        #pragma unroll
        for (int nt = 0; nt < 8; nt++) {
            sc[nt][0] = __expf(sc[nt][0] - mn0); sum0 += sc[nt][0];
            sc[nt][1] = __expf(sc[nt][1] - mn0); sum0 += sc[nt][1];
            sc[nt][2] = __expf(sc[nt][2] - mn1); sum1 += sc[nt][2];
            sc[nt][3] = __expf(sc[nt][3] - mn1); sum1 += sc[nt][3];
        }
        sum0 += __shfl_xor_sync(~0u, sum0, 1);
        sum0 += __shfl_xor_sync(~0u, sum0, 2);
        sum1 += __shfl_xor_sync(~0u, sum1, 1);
        sum1 += __shfl_xor_sync(~0u, sum1, 2);
        lrow0 = lrow0 * cf0 + sum0;
        lrow1 = lrow1 * cf1 + sum1;
        #pragma unroll
        for (int nt = 0; nt < 8; nt++) {
            out[nt][0] *= cf0; out[nt][1] *= cf0;
            out[nt][2] *= cf1; out[nt][3] *= cf1;
        }

        // ---- PV ----
        #pragma unroll
        for (int t = 0; t < 4; t++) {
            uint32_t aP[4];
            aP[0] = h2u(__floats2half2_rn(sc[2*t][0],   sc[2*t][1]));
            aP[1] = h2u(__floats2half2_rn(sc[2*t][2],   sc[2*t][3]));
            aP[2] = h2u(__floats2half2_rn(sc[2*t+1][0], sc[2*t+1][1]));
            aP[3] = h2u(__floats2half2_rn(sc[2*t+1][2], sc[2*t+1][3]));
            #pragma unroll
            for (int ntp = 0; ntp < 4; ntp++) {
                int row = 16 * t + (lane & 7) + ((lane & 8) ? 8 : 0);
                int cc  = 2 * ntp + (lane >> 4);
                uint32_t bv[4];
                ldsm4t(bv, sb + 8192 + row * 128 + ((cc ^ (row & 7)) << 4));
                mma_fp16(out[ntp * 2 + 0], aP, bv);
                mma_fp16(out[ntp * 2 + 1], aP, bv + 2);
            }
        }
        if (c + 2 < nCh) issue_kv(c + 2);
        cp_commit();
    }

    float inv0 = 1.f / lrow0, inv1 = 1.f / lrow1;
    int trow0 = t0 + wid * 16 + (lane >> 2);
    size_t gr0 = (size_t)(trow0 * BATCH + b) * D_MODEL;
    size_t gr1 = (size_t)((trow0 + 8) * BATCH + b) * D_MODEL;
    #pragma unroll
    for (int nt = 0; nt < 8; nt++) {
        int col = hcol + nt * 8 + (lane & 3) * 2;
        *(uint32_t*)(O + gr0 + col) =
            h2u(__floats2half2_rn(out[nt][0] * inv0, out[nt][1] * inv0));
        *(uint32_t*)(O + gr1 + col) =
            h2u(__floats2half2_rn(out[nt][2] * inv1, out[nt][3] * inv1));
    }
}

// ---------------- fp32 -> fp16 convert ---------------------------------------
__global__ __launch_bounds__(256) void cvt_kernel(
    const float4* __restrict__ src, uint2* __restrict__ dst)
{
    size_t i = (size_t)blockIdx.x * 256 + threadIdx.x;
    float4 v = src[i];
    dst[i] = make_uint2(h2u(__floats2half2_rn(v.x, v.y)),
                        h2u(__floats2half2_rn(v.z, v.w)));
}

// ---------------- LayerNorm -> fp16 ------------------------------------------
__global__ __launch_bounds__(256) void ln_kernel(
    const float* __restrict__ x, const float* __restrict__ g,
    const float* __restrict__ b, __half* __restrict__ y)
{
    int row = blockIdx.x;
    const float4* xr = (const float4*)(x + (size_t)row * D_MODEL);
    int tid = threadIdx.x;
    float4 v = xr[tid];
    float s  = v.x + v.y + v.z + v.w;
    float ss = v.x*v.x + v.y*v.y + v.z*v.z + v.w*v.w;
    #pragma unroll
    for (int o = 16; o; o >>= 1) {
        s  += __shfl_xor_sync(~0u, s,  o);
        ss += __shfl_xor_sync(~0u, ss, o);
    }
    __shared__ float smS[8], smSS[8];
    int w = tid >> 5;
    if ((tid & 31) == 0) { smS[w] = s; smSS[w] = ss; }
    __syncthreads();
    if (tid < 32) {
        s  = (tid < 8) ? smS[tid]  : 0.f;
        ss = (tid < 8) ? smSS[tid] : 0.f;
        #pragma unroll
        for (int o = 4; o; o >>= 1) {
            s  += __shfl_xor_sync(~0u, s,  o);
            ss += __shfl_xor_sync(~0u, ss, o);
        }
        if (tid == 0) { smS[0] = s; smSS[0] = ss; }
    }
    __syncthreads();
    float mean = smS[0] * (1.f / D_MODEL);
    float var  = smSS[0] * (1.f / D_MODEL) - mean * mean;
    float rstd = rsqrtf(var + 1e-5f);
    float4 gv = ((const float4*)g)[tid];
    float4 bv = ((const float4*)b)[tid];
    float4 o;
    o.x = (v.x - mean) * rstd * gv.x + bv.x;
    o.y = (v.y - mean) * rstd * gv.y + bv.y;
    o.z = (v.z - mean) * rstd * gv.z + bv.z;
    o.w = (v.w - mean) * rstd * gv.w + bv.w;
    ((uint2*)(y + (size_t)row * D_MODEL))[tid] =
        make_uint2(h2u(__floats2half2_rn(o.x, o.y)),
                   h2u(__floats2half2_rn(o.z, o.w)));
}

// ---------------- orchestration ---------------------------------------------
extern "C" void kernel_launch(void* const* d_in, const int* in_sizes, int n_in,
                              void* d_out, int out_size)
{
    const float* x        = (const float*)d_in[0];
    const float* hid      = (const float*)d_in[1];
    const float* ln1_g    = (const float*)d_in[2];
    const float* ln1_b    = (const float*)d_in[3];
    const float* sa_in_w  = (const float*)d_in[4];
    const float* sa_in_b  = (const float*)d_in[5];
    const float* sa_out_w = (const float*)d_in[6];
    const float* sa_out_b = (const float*)d_in[7];
    const float* ln2_g    = (const float*)d_in[8];
    const float* ln2_b    = (const float*)d_in[9];
    const float* ca_in_w  = (const float*)d_in[10];
    const float* ca_in_b  = (const float*)d_in[11];
    const float* ca_out_w = (const float*)d_in[12];
    const float* ca_out_b = (const float*)d_in[13];
    const float* ln3_g    = (const float*)d_in[14];
    const float* ln3_b    = (const float*)d_in[15];
    const float* fc_w     = (const float*)d_in[16];
    const float* fc_b     = (const float*)d_in[17];
    const float* proj_w   = (const float*)d_in[18];
    const float* proj_b   = (const float*)d_in[19];
    float* out = (float*)d_out;

    __half *w, *hidc, *h, *qkv, *kv, *ctx, *ffn;
    cudaGetSymbolAddress((void**)&w,    g_w);
    cudaGetSymbolAddress((void**)&hidc, g_hid);
    cudaGetSymbolAddress((void**)&h,    g_h);
    cudaGetSymbolAddress((void**)&qkv,  g_qkv);
    cudaGetSymbolAddress((void**)&kv,   g_kv);
    cudaGetSymbolAddress((void**)&ctx,  g_ctx);
    cudaGetSymbolAddress((void**)&ffn,  g_ffn);

    cudaFuncSetAttribute(gemm_fp16,
                         cudaFuncAttributeMaxDynamicSharedMemorySize, GEMM_SMEM);
    cudaFuncSetAttribute(flash_kernel,
                         cudaFuncAttributeMaxDynamicSharedMemorySize, FLASH_SMEM);

    // ---- side stream + events ----
    cudaStream_t sb;
    cudaStreamCreateWithFlags(&sb, cudaStreamNonBlocking);
    cudaEvent_t e0, eSAIN, eSAOUT, eCAIN, eKV, eCAOUT, eFC, ePROJ;
    cudaEventCreateWithFlags(&e0,     cudaEventDisableTiming);
    cudaEventCreateWithFlags(&eSAIN,  cudaEventDisableTiming);
    cudaEventCreateWithFlags(&eSAOUT, cudaEventDisableTiming);
    cudaEventCreateWithFlags(&eCAIN,  cudaEventDisableTiming);
    cudaEventCreateWithFlags(&eKV,    cudaEventDisableTiming);
    cudaEventCreateWithFlags(&eCAOUT, cudaEventDisableTiming);
    cudaEventCreateWithFlags(&eFC,    cudaEventDisableTiming);
    cudaEventCreateWithFlags(&ePROJ,  cudaEventDisableTiming);

    cudaEventRecord(e0, 0);
    cudaStreamWaitEvent(sb, e0, 0);

    // ---- side stream: weight cvts + cross-KV GEMM ----
    cvt_kernel<<<3072, 256, 0, sb>>>((const float4*)sa_in_w,
                                     (uint2*)(w + WS_SA_IN));
    cudaEventRecord(eSAIN, sb);
    cvt_kernel<<<1024, 256, 0, sb>>>((const float4*)sa_out_w,
                                     (uint2*)(w + WS_SA_OUT));
    cudaEventRecord(eSAOUT, sb);
    cvt_kernel<<<3072, 256, 0, sb>>>((const float4*)ca_in_w,
                                     (uint2*)(w + WS_CA_IN));
    cudaEventRecord(eCAIN, sb);
    cvt_kernel<<<16384, 256, 0, sb>>>((const float4*)hid, (uint2*)hidc);
    gemm_fp16<<<dim3(16, 64), 256, GEMM_SMEM, sb>>>(
        hidc, 1024, w + WS_CA_IN + 1048576, 1024,
        ca_in_b + 1024, nullptr, nullptr, kv, 2048, 1024, 0);
    cudaEventRecord(eKV, sb);
    cvt_kernel<<<1024, 256, 0, sb>>>((const float4*)ca_out_w,
                                     (uint2*)(w + WS_CA_OUT));
    cudaEventRecord(eCAOUT, sb);
    cvt_kernel<<<4096, 256, 0, sb>>>((const float4*)fc_w,
                                     (uint2*)(w + WS_FC));
    cudaEventRecord(eFC, sb);
    cvt_kernel<<<4096, 256, 0, sb>>>((const float4*)proj_w,
                                     (uint2*)(w + WS_PROJ));
    cudaEventRecord(ePROJ, sb);

    // ---- main stream: self attention ----
    ln_kernel<<<MQ, 256>>>(x, ln1_g, ln1_b, h);
    cudaStreamWaitEvent(0, eSAIN, 0);
    gemm_fp16<<<dim3(24, 32), 256, GEMM_SMEM>>>(
        h, 1024, w + WS_SA_IN, 1024,
        sa_in_b, nullptr, nullptr, qkv, 3072, 1024, 0);
    flash_kernel<<<dim3(1, 4, 256), 256, FLASH_SMEM>>>(
        qkv, 3072, qkv + 1024, 3072, qkv + 2048, 3072, ctx, T_LEN);
    cudaStreamWaitEvent(0, eSAOUT, 0);
    gemm_fp16<<<dim3(8, 32), 256, GEMM_SMEM>>>(
        ctx, 1024, w + WS_SA_OUT, 1024,
        sa_out_b, x, out, nullptr, 1024, 1024, 0);

    // ---- main stream: cross attention ----
    ln_kernel<<<MQ, 256>>>(out, ln2_g, ln2_b, h);
    cudaStreamWaitEvent(0, eCAIN, 0);
    gemm_fp16<<<dim3(8, 32), 256, GEMM_SMEM>>>(
        h, 1024, w + WS_CA_IN, 1024,
        ca_in_b, nullptr, nullptr, qkv, 1024, 1024, 0);
    cudaStreamWaitEvent(0, eKV, 0);
    flash_kernel<<<dim3(1, 4, 256), 256, FLASH_SMEM>>>(
        qkv, 1024, kv, 2048, kv + 1024, 2048, ctx, S_LEN);
    cudaStreamWaitEvent(0, eCAOUT, 0);
    gemm_fp16<<<dim3(8, 32), 256, GEMM_SMEM>>>(
        ctx, 1024, w + WS_CA_OUT, 1024,
        ca_out_b, out, out, nullptr, 1024, 1024, 0);

    // ---- main stream: MLP ----
    ln_kernel<<<MQ, 256>>>(out, ln3_g, ln3_b, h);
    cudaStreamWaitEvent(0, eFC, 0);
    gemm_fp16<<<dim3(32, 32), 256, GEMM_SMEM>>>(
        h, 1024, w + WS_FC, 1024,
        fc_b, nullptr, nullptr, ffn, 4096, 1024, 1);
    cudaStreamWaitEvent(0, ePROJ, 0);
    gemm_fp16<<<dim3(8, 32), 256, GEMM_SMEM>>>(
        ffn, 4096, w + WS_PROJ, 4096,
        proj_b, out, out, nullptr, 1024, 4096, 0);
}

// round 16
// speedup vs baseline: 1.2329x; 1.2329x over previous
#include <cuda_runtime.h>
#include <cuda_fp16.h>
#include <math.h>
#include <stdint.h>

#define D_MODEL 1024
#define N_HEAD  16
#define T_LEN   512
#define S_LEN   1024
#define BATCH   16
#define MQ      (T_LEN * BATCH)   /* 8192  query rows  */
#define MKV     (S_LEN * BATCH)   /* 16384 kv rows     */

// ---------------- scratch (static device globals; no allocation) ------------
#define WS_SA_IN  0u
#define WS_SA_OUT (3u*1024*1024)
#define WS_CA_IN  (4u*1024*1024)
#define WS_CA_OUT (7u*1024*1024)
#define WS_FC     (8u*1024*1024)
#define WS_PROJ   (12u*1024*1024)
#define WS_TOTAL  (16u*1024*1024)
__device__ __half g_w  [WS_TOTAL];            // fp16 weights
__device__ __half g_hid[MKV * D_MODEL];       // fp16 hidden_states
__device__ __half g_h  [MQ * D_MODEL];        // LN output
__device__ __half g_qkv[MQ * 3 * D_MODEL];
__device__ __half g_kv [MKV * 2 * D_MODEL];
__device__ __half g_ctx[MQ * D_MODEL];
__device__ __half g_ffn[MQ * 4 * D_MODEL];

__device__ __forceinline__ uint32_t h2u(__half2 x) {
    return *reinterpret_cast<uint32_t*>(&x);
}
__device__ __forceinline__ uint32_t smem_u32(const void* p) {
    uint32_t a;
    asm("{ .reg .u64 t; cvta.to.shared.u64 t, %1; cvt.u32.u64 %0, t; }"
        : "=r"(a) : "l"(p));
    return a;
}
__device__ __forceinline__ void cp_async16(uint32_t s, const void* g) {
    asm volatile("cp.async.cg.shared.global [%0], [%1], 16;" :: "r"(s), "l"(g));
}
__device__ __forceinline__ void cp_commit() {
    asm volatile("cp.async.commit_group;");
}
__device__ __forceinline__ void cp_wait1() {
    asm volatile("cp.async.wait_group 1;");
}
__device__ __forceinline__ void ldsm4(uint32_t* r, uint32_t addr) {
    asm volatile("ldmatrix.sync.aligned.m8n8.x4.shared.b16 {%0,%1,%2,%3}, [%4];"
                 : "=r"(r[0]), "=r"(r[1]), "=r"(r[2]), "=r"(r[3]) : "r"(addr));
}
__device__ __forceinline__ void ldsm4t(uint32_t* r, uint32_t addr) {
    asm volatile("ldmatrix.sync.aligned.m8n8.x4.trans.shared.b16 {%0,%1,%2,%3}, [%4];"
                 : "=r"(r[0]), "=r"(r[1]), "=r"(r[2]), "=r"(r[3]) : "r"(addr));
}
__device__ __forceinline__ void mma_fp16(float* c, const uint32_t* a,
                                         const uint32_t* b) {
    asm volatile(
        "mma.sync.aligned.m16n8k16.row.col.f32.f16.f16.f32 "
        "{%0,%1,%2,%3}, {%4,%5,%6,%7}, {%8,%9}, {%0,%1,%2,%3};"
        : "+f"(c[0]), "+f"(c[1]), "+f"(c[2]), "+f"(c[3])
        : "r"(a[0]), "r"(a[1]), "r"(a[2]), "r"(a[3]),
          "r"(b[0]), "r"(b[1]));
}

// ======================= FP16 single-pass GEMM ==============================
// Tile 128x128, BK=64 (128B rows, SW128 swizzle), 3-stage cp.async,
// ONE sync/iter: wait (chunk c own-copies) -> sync (visibility + stage free)
// -> issue c+2 (overlaps with compute) -> compute c.   [R14, committed best]
__global__ __launch_bounds__(256, 2) void gemm_fp16(
    const __half* __restrict__ A, int lda,
    const __half* __restrict__ B, int ldb,
    const float* __restrict__ bias,
    const float* __restrict__ res,
    float* __restrict__ Cf, __half* __restrict__ Ch,
    int ldc, int K, int act)
{
    extern __shared__ char dsm[];
    const uint32_t smem_base = smem_u32(dsm);
    const int tid = threadIdx.x, wid = tid >> 5, lane = tid & 31;
    const int wm = wid >> 1, wn = wid & 1;
    const int m0 = blockIdx.y * 128, n0 = blockIdx.x * 128;

    float acc[2][8][4];
    #pragma unroll
    for (int i = 0; i < 2; i++)
        #pragma unroll
        for (int j = 0; j < 8; j++)
            #pragma unroll
            for (int q = 0; q < 4; q++) acc[i][j][q] = 0.f;

    const int nCh = K >> 6;
    auto issue = [&](int c) {
        const int k0 = c << 6;
        const uint32_t sb = smem_base + (c % 3) * 32768;
        #pragma unroll
        for (int it = 0; it < 4; it++) {
            int idx = tid + (it << 8);
            int r = idx >> 3, q = idx & 7;
            uint32_t so = sb + r * 128 + ((q ^ (r & 7)) << 4);
            cp_async16(so, A + (size_t)(m0 + r) * lda + k0 + q * 8);
        }
        #pragma unroll
        for (int it = 0; it < 4; it++) {
            int idx = tid + (it << 8);
            int n = idx >> 3, q = idx & 7;
            uint32_t so = sb + 16384 + n * 128 + ((q ^ (n & 7)) << 4);
            cp_async16(so, B + (size_t)(n0 + n) * ldb + k0 + q * 8);
        }
    };

    issue(0); cp_commit();
    issue(1); cp_commit();

    for (int c = 0; c < nCh; c++) {
        cp_wait1();          // own copies of chunk c done (c+1 in flight)
        __syncthreads();     // visibility; stage (c-1)%3 free
        if (c + 2 < nCh) issue(c + 2);   // overlap copies with compute
        cp_commit();
        const uint32_t sb = smem_base + (c % 3) * 32768;
        #pragma unroll
        for (int ks = 0; ks < 4; ks++) {
            uint32_t a[2][4];
            #pragma unroll
            for (int mt = 0; mt < 2; mt++) {
                int row = wm * 32 + mt * 16 + (lane & 15);
                int cc  = 2 * ks + (lane >> 4);
                ldsm4(a[mt], sb + row * 128 + ((cc ^ (row & 7)) << 4));
            }
            #pragma unroll
            for (int ntp = 0; ntp < 4; ntp++) {
                int nrow = wn * 64 + ntp * 16 + (lane & 7)
                         + ((lane & 16) ? 8 : 0);
                int cc   = 2 * ks + ((lane >> 3) & 1);
                uint32_t b[4];
                ldsm4(b, sb + 16384 + nrow * 128 + ((cc ^ (nrow & 7)) << 4));
                #pragma unroll
                for (int half = 0; half < 2; half++) {
                    int nt = ntp * 2 + half;
                    mma_fp16(acc[0][nt], a[0], b + half * 2);
                    mma_fp16(acc[1][nt], a[1], b + half * 2);
                }
            }
        }
    }

    const int r0 = m0 + wm * 32 + (lane >> 2);
    const int c0 = n0 + wn * 64 + (lane & 3) * 2;
    #pragma unroll
    for (int mt = 0; mt < 2; mt++) {
        #pragma unroll
        for (int nt = 0; nt < 8; nt++) {
            int col = c0 + nt * 8;
            float2 bv = make_float2(0.f, 0.f);
            if (bias) bv = *(const float2*)(bias + col);
            #pragma unroll
            for (int hrow = 0; hrow < 2; hrow++) {
                int row = r0 + mt * 16 + hrow * 8;
                float2 vv;
                vv.x = acc[mt][nt][hrow * 2 + 0] + bv.x;
                vv.y = acc[mt][nt][hrow * 2 + 1] + bv.y;
                size_t co = (size_t)row * ldc + col;
                if (res) {
                    float2 rr = *(const float2*)(res + co);
                    vv.x += rr.x; vv.y += rr.y;
                }
                if (act) {
                    vv.x = vv.x / (1.f + __expf(-1.702f * vv.x));
                    vv.y = vv.y / (1.f + __expf(-1.702f * vv.y));
                }
                if (Cf) {
                    *(float2*)(Cf + co) = vv;
                } else {
                    *(uint32_t*)(Ch + co) = h2u(__floats2half2_rn(vv.x, vv.y));
                }
            }
        }
    }
}

// ======================= flash attention (fp16, 3-stage, 1 sync/iter) =======
// Grid (1, T/128, 256). smem: Q 16KB + 3 KV stages x 16KB = 64KB.
// __launch_bounds__(256,2): force <=128 regs so 2 CTAs/SM co-reside.
#define FLASH_SMEM (16384 + 3 * 16384)
__global__ __launch_bounds__(256, 2) void flash_kernel(
    const __half* __restrict__ Q, int ldq,
    const __half* __restrict__ K, int ldk,
    const __half* __restrict__ V, int ldv,
    __half* __restrict__ O, int S)
{
    extern __shared__ char dsm[];
    const uint32_t sQ  = smem_u32(dsm);
    const uint32_t sKV = sQ + 16384;
    const int tid = threadIdx.x, wid = tid >> 5, lane = tid & 31;
    const int z = blockIdx.z, b = z & 15, h = z >> 4;
    const int t0 = blockIdx.y * 128;
    const int hcol = h * 64;

    #pragma unroll
    for (int p = 0; p < 4; p++) {
        int idx = tid + (p << 8);
        int r = idx >> 3, q = idx & 7;
        uint32_t so = sQ + r * 128 + ((q ^ (r & 7)) << 4);
        cp_async16(so, Q + (size_t)((t0 + r) * BATCH + b) * ldq + hcol + q * 8);
    }
    auto issue_kv = [&](int c) {
        int s0 = c << 6;
        uint32_t sb = sKV + (c % 3) * 16384;
        #pragma unroll
        for (int p = 0; p < 2; p++) {
            int idx = tid + (p << 8);
            int r = idx >> 3, q = idx & 7;
            uint32_t so = sb + r * 128 + ((q ^ (r & 7)) << 4);
            size_t rowg = (size_t)((s0 + r) * BATCH + b);
            cp_async16(so,        K + rowg * ldk + hcol + q * 8);
            cp_async16(so + 8192, V + rowg * ldv + hcol + q * 8);
        }
    };
    issue_kv(0); cp_commit();
    issue_kv(1); cp_commit();

    float out[8][4];
    #pragma unroll
    for (int i = 0; i < 8; i++)
        #pragma unroll
        for (int j = 0; j < 4; j++) out[i][j] = 0.f;
    float mrow0 = -1e30f, mrow1 = -1e30f, lrow0 = 0.f, lrow1 = 0.f;

    const int nCh = S >> 6;
    for (int c = 0; c < nCh; c++) {
        cp_wait1();
        __syncthreads();
        const uint32_t sb = sKV + (c % 3) * 16384;

        // ---- scores ----
        float sc[8][4];
        #pragma unroll
        for (int i = 0; i < 8; i++)
            #pragma unroll
            for (int j = 0; j < 4; j++) sc[i][j] = 0.f;
        #pragma unroll
        for (int ks = 0; ks < 4; ks++) {
            uint32_t a[4];
            {
                int row = wid * 16 + (lane & 15);
                int cc  = 2 * ks + (lane >> 4);
                ldsm4(a, sQ + row * 128 + ((cc ^ (row & 7)) << 4));
            }
            #pragma unroll
            for (int ntp = 0; ntp < 4; ntp++) {
                int nrow = ntp * 16 + (lane & 7) + ((lane & 16) ? 8 : 0);
                int cc   = 2 * ks + ((lane >> 3) & 1);
                uint32_t bq[4];
                ldsm4(bq, sb + nrow * 128 + ((cc ^ (nrow & 7)) << 4));
                mma_fp16(sc[ntp * 2 + 0], a, bq);
                mma_fp16(sc[ntp * 2 + 1], a, bq + 2);
            }
        }

        // ---- online softmax ----
        float mx0 = -1e30f, mx1 = -1e30f;
        #pragma unroll
        for (int nt = 0; nt < 8; nt++) {
            sc[nt][0] *= 0.125f; sc[nt][1] *= 0.125f;
            sc[nt][2] *= 0.125f; sc[nt][3] *= 0.125f;
            mx0 = fmaxf(mx0, fmaxf(sc[nt][0], sc[nt][1]));
            mx1 = fmaxf(mx1, fmaxf(sc[nt][2], sc[nt][3]));
        }
        mx0 = fmaxf(mx0, __shfl_xor_sync(~0u, mx0, 1));
        mx0 = fmaxf(mx0, __shfl_xor_sync(~0u, mx0, 2));
        mx1 = fmaxf(mx1, __shfl_xor_sync(~0u, mx1, 1));
        mx1 = fmaxf(mx1, __shfl_xor_sync(~0u, mx1, 2));
        float mn0 = fmaxf(mrow0, mx0), mn1 = fmaxf(mrow1, mx1);
        float cf0 = __expf(mrow0 - mn0), cf1 = __expf(mrow1 - mn1);
        mrow0 = mn0; mrow1 = mn1;
        float sum0 = 0.f, sum1 = 0.f;
        #pragma unroll
        for (int nt = 0; nt < 8; nt++) {
            sc[nt][0] = __expf(sc[nt][0] - mn0); sum0 += sc[nt][0];
            sc[nt][1] = __expf(sc[nt][1] - mn0); sum0 += sc[nt][1];
            sc[nt][2] = __expf(sc[nt][2] - mn1); sum1 += sc[nt][2];
            sc[nt][3] = __expf(sc[nt][3] - mn1); sum1 += sc[nt][3];
        }
        sum0 += __shfl_xor_sync(~0u, sum0, 1);
        sum0 += __shfl_xor_sync(~0u, sum0, 2);
        sum1 += __shfl_xor_sync(~0u, sum1, 1);
        sum1 += __shfl_xor_sync(~0u, sum1, 2);
        lrow0 = lrow0 * cf0 + sum0;
        lrow1 = lrow1 * cf1 + sum1;
        #pragma unroll
        for (int nt = 0; nt < 8; nt++) {
            out[nt][0] *= cf0; out[nt][1] *= cf0;
            out[nt][2] *= cf1; out[nt][3] *= cf1;
        }

        // ---- PV ----
        #pragma unroll
        for (int t = 0; t < 4; t++) {
            uint32_t aP[4];
            aP[0] = h2u(__floats2half2_rn(sc[2*t][0],   sc[2*t][1]));
            aP[1] = h2u(__floats2half2_rn(sc[2*t][2],   sc[2*t][3]));
            aP[2] = h2u(__floats2half2_rn(sc[2*t+1][0], sc[2*t+1][1]));
            aP[3] = h2u(__floats2half2_rn(sc[2*t+1][2], sc[2*t+1][3]));
            #pragma unroll
            for (int ntp = 0; ntp < 4; ntp++) {
                int row = 16 * t + (lane & 7) + ((lane & 8) ? 8 : 0);
                int cc  = 2 * ntp + (lane >> 4);
                uint32_t bv[4];
                ldsm4t(bv, sb + 8192 + row * 128 + ((cc ^ (row & 7)) << 4));
                mma_fp16(out[ntp * 2 + 0], aP, bv);
                mma_fp16(out[ntp * 2 + 1], aP, bv + 2);
            }
        }
        if (c + 2 < nCh) issue_kv(c + 2);
        cp_commit();
    }

    float inv0 = 1.f / lrow0, inv1 = 1.f / lrow1;
    int trow0 = t0 + wid * 16 + (lane >> 2);
    size_t gr0 = (size_t)(trow0 * BATCH + b) * D_MODEL;
    size_t gr1 = (size_t)((trow0 + 8) * BATCH + b) * D_MODEL;
    #pragma unroll
    for (int nt = 0; nt < 8; nt++) {
        int col = hcol + nt * 8 + (lane & 3) * 2;
        *(uint32_t*)(O + gr0 + col) =
            h2u(__floats2half2_rn(out[nt][0] * inv0, out[nt][1] * inv0));
        *(uint32_t*)(O + gr1 + col) =
            h2u(__floats2half2_rn(out[nt][2] * inv1, out[nt][3] * inv1));
    }
}

// ---------------- fp32 -> fp16 convert ---------------------------------------
__global__ __launch_bounds__(256) void cvt_kernel(
    const float4* __restrict__ src, uint2* __restrict__ dst)
{
    size_t i = (size_t)blockIdx.x * 256 + threadIdx.x;
    float4 v = src[i];
    dst[i] = make_uint2(h2u(__floats2half2_rn(v.x, v.y)),
                        h2u(__floats2half2_rn(v.z, v.w)));
}

// ---------------- LayerNorm -> fp16 ------------------------------------------
__global__ __launch_bounds__(256) void ln_kernel(
    const float* __restrict__ x, const float* __restrict__ g,
    const float* __restrict__ b, __half* __restrict__ y)
{
    int row = blockIdx.x;
    const float4* xr = (const float4*)(x + (size_t)row * D_MODEL);
    int tid = threadIdx.x;
    float4 v = xr[tid];
    float s  = v.x + v.y + v.z + v.w;
    float ss = v.x*v.x + v.y*v.y + v.z*v.z + v.w*v.w;
    #pragma unroll
    for (int o = 16; o; o >>= 1) {
        s  += __shfl_xor_sync(~0u, s,  o);
        ss += __shfl_xor_sync(~0u, ss, o);
    }
    __shared__ float smS[8], smSS[8];
    int w = tid >> 5;
    if ((tid & 31) == 0) { smS[w] = s; smSS[w] = ss; }
    __syncthreads();
    if (tid < 32) {
        s  = (tid < 8) ? smS[tid]  : 0.f;
        ss = (tid < 8) ? smSS[tid] : 0.f;
        #pragma unroll
        for (int o = 4; o; o >>= 1) {
            s  += __shfl_xor_sync(~0u, s,  o);
            ss += __shfl_xor_sync(~0u, ss, o);
        }
        if (tid == 0) { smS[0] = s; smSS[0] = ss; }
    }
    __syncthreads();
    float mean = smS[0] * (1.f / D_MODEL);
    float var  = smSS[0] * (1.f / D_MODEL) - mean * mean;
    float rstd = rsqrtf(var + 1e-5f);
    float4 gv = ((const float4*)g)[tid];
    float4 bv = ((const float4*)b)[tid];
    float4 o;
    o.x = (v.x - mean) * rstd * gv.x + bv.x;
    o.y = (v.y - mean) * rstd * gv.y + bv.y;
    o.z = (v.z - mean) * rstd * gv.z + bv.z;
    o.w = (v.w - mean) * rstd * gv.w + bv.w;
    ((uint2*)(y + (size_t)row * D_MODEL))[tid] =
        make_uint2(h2u(__floats2half2_rn(o.x, o.y)),
                   h2u(__floats2half2_rn(o.z, o.w)));
}

// ---------------- orchestration ---------------------------------------------
extern "C" void kernel_launch(void* const* d_in, const int* in_sizes, int n_in,
                              void* d_out, int out_size)
{
    const float* x        = (const float*)d_in[0];
    const float* hid      = (const float*)d_in[1];
    const float* ln1_g    = (const float*)d_in[2];
    const float* ln1_b    = (const float*)d_in[3];
    const float* sa_in_w  = (const float*)d_in[4];
    const float* sa_in_b  = (const float*)d_in[5];
    const float* sa_out_w = (const float*)d_in[6];
    const float* sa_out_b = (const float*)d_in[7];
    const float* ln2_g    = (const float*)d_in[8];
    const float* ln2_b    = (const float*)d_in[9];
    const float* ca_in_w  = (const float*)d_in[10];
    const float* ca_in_b  = (const float*)d_in[11];
    const float* ca_out_w = (const float*)d_in[12];
    const float* ca_out_b = (const float*)d_in[13];
    const float* ln3_g    = (const float*)d_in[14];
    const float* ln3_b    = (const float*)d_in[15];
    const float* fc_w     = (const float*)d_in[16];
    const float* fc_b     = (const float*)d_in[17];
    const float* proj_w   = (const float*)d_in[18];
    const float* proj_b   = (const float*)d_in[19];
    float* out = (float*)d_out;

    __half *w, *hidc, *h, *qkv, *kv, *ctx, *ffn;
    cudaGetSymbolAddress((void**)&w,    g_w);
    cudaGetSymbolAddress((void**)&hidc, g_hid);
    cudaGetSymbolAddress((void**)&h,    g_h);
    cudaGetSymbolAddress((void**)&qkv,  g_qkv);
    cudaGetSymbolAddress((void**)&kv,   g_kv);
    cudaGetSymbolAddress((void**)&ctx,  g_ctx);
    cudaGetSymbolAddress((void**)&ffn,  g_ffn);

    const int SMG = 98304;
    cudaFuncSetAttribute(gemm_fp16,
                         cudaFuncAttributeMaxDynamicSharedMemorySize, SMG);
    cudaFuncSetAttribute(flash_kernel,
                         cudaFuncAttributeMaxDynamicSharedMemorySize, FLASH_SMEM);

    // ---- side stream + events ----
    cudaStream_t sb;
    cudaStreamCreateWithFlags(&sb, cudaStreamNonBlocking);
    cudaEvent_t e0, eSAIN, eSAOUT, eCAIN, eKV, eCAOUT, eFC, ePROJ;
    cudaEventCreateWithFlags(&e0,     cudaEventDisableTiming);
    cudaEventCreateWithFlags(&eSAIN,  cudaEventDisableTiming);
    cudaEventCreateWithFlags(&eSAOUT, cudaEventDisableTiming);
    cudaEventCreateWithFlags(&eCAIN,  cudaEventDisableTiming);
    cudaEventCreateWithFlags(&eKV,    cudaEventDisableTiming);
    cudaEventCreateWithFlags(&eCAOUT, cudaEventDisableTiming);
    cudaEventCreateWithFlags(&eFC,    cudaEventDisableTiming);
    cudaEventCreateWithFlags(&ePROJ,  cudaEventDisableTiming);

    cudaEventRecord(e0, 0);
    cudaStreamWaitEvent(sb, e0, 0);

    // ---- side stream: weight cvts + cross-KV GEMM ----
    cvt_kernel<<<3072, 256, 0, sb>>>((const float4*)sa_in_w,
                                     (uint2*)(w + WS_SA_IN));
    cudaEventRecord(eSAIN, sb);
    cvt_kernel<<<1024, 256, 0, sb>>>((const float4*)sa_out_w,
                                     (uint2*)(w + WS_SA_OUT));
    cudaEventRecord(eSAOUT, sb);
    cvt_kernel<<<3072, 256, 0, sb>>>((const float4*)ca_in_w,
                                     (uint2*)(w + WS_CA_IN));
    cudaEventRecord(eCAIN, sb);
    cvt_kernel<<<16384, 256, 0, sb>>>((const float4*)hid, (uint2*)hidc);
    gemm_fp16<<<dim3(16, 128), 256, SMG, sb>>>(
        hidc, 1024, w + WS_CA_IN + 1048576, 1024,
        ca_in_b + 1024, nullptr, nullptr, kv, 2048, 1024, 0);
    cudaEventRecord(eKV, sb);
    cvt_kernel<<<1024, 256, 0, sb>>>((const float4*)ca_out_w,
                                     (uint2*)(w + WS_CA_OUT));
    cudaEventRecord(eCAOUT, sb);
    cvt_kernel<<<4096, 256, 0, sb>>>((const float4*)fc_w,
                                     (uint2*)(w + WS_FC));
    cudaEventRecord(eFC, sb);
    cvt_kernel<<<4096, 256, 0, sb>>>((const float4*)proj_w,
                                     (uint2*)(w + WS_PROJ));
    cudaEventRecord(ePROJ, sb);

    // ---- main stream: self attention ----
    ln_kernel<<<MQ, 256>>>(x, ln1_g, ln1_b, h);
    cudaStreamWaitEvent(0, eSAIN, 0);
    gemm_fp16<<<dim3(24, 64), 256, SMG>>>(
        h, 1024, w + WS_SA_IN, 1024,
        sa_in_b, nullptr, nullptr, qkv, 3072, 1024, 0);
    flash_kernel<<<dim3(1, 4, 256), 256, FLASH_SMEM>>>(
        qkv, 3072, qkv + 1024, 3072, qkv + 2048, 3072, ctx, T_LEN);
    cudaStreamWaitEvent(0, eSAOUT, 0);
    gemm_fp16<<<dim3(8, 64), 256, SMG>>>(
        ctx, 1024, w + WS_SA_OUT, 1024,
        sa_out_b, x, out, nullptr, 1024, 1024, 0);

    // ---- main stream: cross attention ----
    ln_kernel<<<MQ, 256>>>(out, ln2_g, ln2_b, h);
    cudaStreamWaitEvent(0, eCAIN, 0);
    gemm_fp16<<<dim3(8, 64), 256, SMG>>>(
        h, 1024, w + WS_CA_IN, 1024,
        ca_in_b, nullptr, nullptr, qkv, 1024, 1024, 0);
    cudaStreamWaitEvent(0, eKV, 0);
    flash_kernel<<<dim3(1, 4, 256), 256, FLASH_SMEM>>>(
        qkv, 1024, kv, 2048, kv + 1024, 2048, ctx, S_LEN);
    cudaStreamWaitEvent(0, eCAOUT, 0);
    gemm_fp16<<<dim3(8, 64), 256, SMG>>>(
        ctx, 1024, w + WS_CA_OUT, 1024,
        ca_out_b, out, out, nullptr, 1024, 1024, 0);

    // ---- main stream: MLP ----
    ln_kernel<<<MQ, 256>>>(out, ln3_g, ln3_b, h);
    cudaStreamWaitEvent(0, eFC, 0);
    gemm_fp16<<<dim3(32, 64), 256, SMG>>>(
        h, 1024, w + WS_FC, 1024,
        fc_b, nullptr, nullptr, ffn, 4096, 1024, 1);
    cudaStreamWaitEvent(0, ePROJ, 0);
    gemm_fp16<<<dim3(8, 64), 256, SMG>>>(
        ffn, 4096, w + WS_PROJ, 4096,
        proj_b, out, out, nullptr, 1024, 4096, 0);
}

// round 17
// speedup vs baseline: 1.2361x; 1.0026x over previous
#include <cuda_runtime.h>
#include <cuda_fp16.h>
#include <math.h>
#include <stdint.h>

#define D_MODEL 1024
#define N_HEAD  16
#define T_LEN   512
#define S_LEN   1024
#define BATCH   16
#define MQ      (T_LEN * BATCH)   /* 8192  query rows  */
#define MKV     (S_LEN * BATCH)   /* 16384 kv rows     */

// ---------------- scratch (static device globals; no allocation) ------------
#define WS_SA_IN  0u
#define WS_SA_OUT (3u*1024*1024)
#define WS_CA_IN  (4u*1024*1024)
#define WS_CA_OUT (7u*1024*1024)
#define WS_FC     (8u*1024*1024)
#define WS_PROJ   (12u*1024*1024)
#define WS_TOTAL  (16u*1024*1024)
__device__ __half g_w  [WS_TOTAL];            // fp16 weights
__device__ __half g_hid[MKV * D_MODEL];       // fp16 hidden_states
__device__ __half g_h  [MQ * D_MODEL];        // LN output
__device__ __half g_qkv[MQ * 3 * D_MODEL];
__device__ __half g_kv [MKV * 2 * D_MODEL];
__device__ __half g_ctx[MQ * D_MODEL];
__device__ __half g_ffn[MQ * 4 * D_MODEL];

__device__ __forceinline__ uint32_t h2u(__half2 x) {
    return *reinterpret_cast<uint32_t*>(&x);
}
__device__ __forceinline__ uint32_t smem_u32(const void* p) {
    uint32_t a;
    asm("{ .reg .u64 t; cvta.to.shared.u64 t, %1; cvt.u32.u64 %0, t; }"
        : "=r"(a) : "l"(p));
    return a;
}
__device__ __forceinline__ void cp_async16(uint32_t s, const void* g) {
    asm volatile("cp.async.cg.shared.global [%0], [%1], 16;" :: "r"(s), "l"(g));
}
__device__ __forceinline__ void cp_commit() {
    asm volatile("cp.async.commit_group;");
}
__device__ __forceinline__ void cp_wait1() {
    asm volatile("cp.async.wait_group 1;");
}
__device__ __forceinline__ void ldsm4(uint32_t* r, uint32_t addr) {
    asm volatile("ldmatrix.sync.aligned.m8n8.x4.shared.b16 {%0,%1,%2,%3}, [%4];"
                 : "=r"(r[0]), "=r"(r[1]), "=r"(r[2]), "=r"(r[3]) : "r"(addr));
}
__device__ __forceinline__ void ldsm4t(uint32_t* r, uint32_t addr) {
    asm volatile("ldmatrix.sync.aligned.m8n8.x4.trans.shared.b16 {%0,%1,%2,%3}, [%4];"
                 : "=r"(r[0]), "=r"(r[1]), "=r"(r[2]), "=r"(r[3]) : "r"(addr));
}
__device__ __forceinline__ void mma_fp16(float* c, const uint32_t* a,
                                         const uint32_t* b) {
    asm volatile(
        "mma.sync.aligned.m16n8k16.row.col.f32.f16.f16.f32 "
        "{%0,%1,%2,%3}, {%4,%5,%6,%7}, {%8,%9}, {%0,%1,%2,%3};"
        : "+f"(c[0]), "+f"(c[1]), "+f"(c[2]), "+f"(c[3])
        : "r"(a[0]), "r"(a[1]), "r"(a[2]), "r"(a[3]),
          "r"(b[0]), "r"(b[1]));
}

// ======================= FP16 single-pass GEMM ==============================
// Tile 128x128, BK=64 (128B rows, SW128 swizzle), 3-stage cp.async,
// ONE sync/iter: wait -> sync -> issue c+2 -> compute c.   [R14 structure]
// scale_ncols: columns < scale_ncols are multiplied by 0.125 after bias
// (folds attention 1/sqrt(d) into Q at the producing GEMM).
__global__ __launch_bounds__(256, 2) void gemm_fp16(
    const __half* __restrict__ A, int lda,
    const __half* __restrict__ B, int ldb,
    const float* __restrict__ bias,
    const float* __restrict__ res,
    float* __restrict__ Cf, __half* __restrict__ Ch,
    int ldc, int K, int act, int scale_ncols)
{
    extern __shared__ char dsm[];
    const uint32_t smem_base = smem_u32(dsm);
    const int tid = threadIdx.x, wid = tid >> 5, lane = tid & 31;
    const int wm = wid >> 1, wn = wid & 1;
    const int m0 = blockIdx.y * 128, n0 = blockIdx.x * 128;

    float acc[2][8][4];
    #pragma unroll
    for (int i = 0; i < 2; i++)
        #pragma unroll
        for (int j = 0; j < 8; j++)
            #pragma unroll
            for (int q = 0; q < 4; q++) acc[i][j][q] = 0.f;

    const int nCh = K >> 6;
    auto issue = [&](int c) {
        const int k0 = c << 6;
        const uint32_t sb = smem_base + (c % 3) * 32768;
        #pragma unroll
        for (int it = 0; it < 4; it++) {
            int idx = tid + (it << 8);
            int r = idx >> 3, q = idx & 7;
            uint32_t so = sb + r * 128 + ((q ^ (r & 7)) << 4);
            cp_async16(so, A + (size_t)(m0 + r) * lda + k0 + q * 8);
        }
        #pragma unroll
        for (int it = 0; it < 4; it++) {
            int idx = tid + (it << 8);
            int n = idx >> 3, q = idx & 7;
            uint32_t so = sb + 16384 + n * 128 + ((q ^ (n & 7)) << 4);
            cp_async16(so, B + (size_t)(n0 + n) * ldb + k0 + q * 8);
        }
    };

    issue(0); cp_commit();
    issue(1); cp_commit();

    for (int c = 0; c < nCh; c++) {
        cp_wait1();
        __syncthreads();
        if (c + 2 < nCh) issue(c + 2);
        cp_commit();
        const uint32_t sb = smem_base + (c % 3) * 32768;
        #pragma unroll
        for (int ks = 0; ks < 4; ks++) {
            uint32_t a[2][4];
            #pragma unroll
            for (int mt = 0; mt < 2; mt++) {
                int row = wm * 32 + mt * 16 + (lane & 15);
                int cc  = 2 * ks + (lane >> 4);
                ldsm4(a[mt], sb + row * 128 + ((cc ^ (row & 7)) << 4));
            }
            #pragma unroll
            for (int ntp = 0; ntp < 4; ntp++) {
                int nrow = wn * 64 + ntp * 16 + (lane & 7)
                         + ((lane & 16) ? 8 : 0);
                int cc   = 2 * ks + ((lane >> 3) & 1);
                uint32_t b[4];
                ldsm4(b, sb + 16384 + nrow * 128 + ((cc ^ (nrow & 7)) << 4));
                #pragma unroll
                for (int half = 0; half < 2; half++) {
                    int nt = ntp * 2 + half;
                    mma_fp16(acc[0][nt], a[0], b + half * 2);
                    mma_fp16(acc[1][nt], a[1], b + half * 2);
                }
            }
        }
    }

    const int r0 = m0 + wm * 32 + (lane >> 2);
    const int c0 = n0 + wn * 64 + (lane & 3) * 2;
    #pragma unroll
    for (int mt = 0; mt < 2; mt++) {
        #pragma unroll
        for (int nt = 0; nt < 8; nt++) {
            int col = c0 + nt * 8;
            float2 bv = make_float2(0.f, 0.f);
            if (bias) bv = *(const float2*)(bias + col);
            float sc = (col < scale_ncols) ? 0.125f : 1.f;
            #pragma unroll
            for (int hrow = 0; hrow < 2; hrow++) {
                int row = r0 + mt * 16 + hrow * 8;
                float2 vv;
                vv.x = (acc[mt][nt][hrow * 2 + 0] + bv.x) * sc;
                vv.y = (acc[mt][nt][hrow * 2 + 1] + bv.y) * sc;
                size_t co = (size_t)row * ldc + col;
                if (res) {
                    float2 rr = *(const float2*)(res + co);
                    vv.x += rr.x; vv.y += rr.y;
                }
                if (act) {
                    vv.x = vv.x / (1.f + __expf(-1.702f * vv.x));
                    vv.y = vv.y / (1.f + __expf(-1.702f * vv.y));
                }
                if (Cf) {
                    *(float2*)(Cf + co) = vv;
                } else {
                    *(uint32_t*)(Ch + co) = h2u(__floats2half2_rn(vv.x, vv.y));
                }
            }
        }
    }
}

// ======================= flash attention (fp16, 3-stage, 1 sync/iter) =======
// Q pre-scaled by 1/sqrt(d) at the producing GEMM; Q fragments hoisted
// out of the S-loop (invariant). smem: Q 16KB + 3 KV stages x 16KB.
#define FLASH_SMEM (16384 + 3 * 16384)
__global__ __launch_bounds__(256, 2) void flash_kernel(
    const __half* __restrict__ Q, int ldq,
    const __half* __restrict__ K, int ldk,
    const __half* __restrict__ V, int ldv,
    __half* __restrict__ O, int S)
{
    extern __shared__ char dsm[];
    const uint32_t sQ  = smem_u32(dsm);
    const uint32_t sKV = sQ + 16384;
    const int tid = threadIdx.x, wid = tid >> 5, lane = tid & 31;
    const int z = blockIdx.z, b = z & 15, h = z >> 4;
    const int t0 = blockIdx.y * 128;
    const int hcol = h * 64;

    #pragma unroll
    for (int p = 0; p < 4; p++) {
        int idx = tid + (p << 8);
        int r = idx >> 3, q = idx & 7;
        uint32_t so = sQ + r * 128 + ((q ^ (r & 7)) << 4);
        cp_async16(so, Q + (size_t)((t0 + r) * BATCH + b) * ldq + hcol + q * 8);
    }
    auto issue_kv = [&](int c) {
        int s0 = c << 6;
        uint32_t sb = sKV + (c % 3) * 16384;
        #pragma unroll
        for (int p = 0; p < 2; p++) {
            int idx = tid + (p << 8);
            int r = idx >> 3, q = idx & 7;
            uint32_t so = sb + r * 128 + ((q ^ (r & 7)) << 4);
            size_t rowg = (size_t)((s0 + r) * BATCH + b);
            cp_async16(so,        K + rowg * ldk + hcol + q * 8);
            cp_async16(so + 8192, V + rowg * ldv + hcol + q * 8);
        }
    };
    issue_kv(0); cp_commit();
    issue_kv(1); cp_commit();

    float out[8][4];
    #pragma unroll
    for (int i = 0; i < 8; i++)
        #pragma unroll
        for (int j = 0; j < 4; j++) out[i][j] = 0.f;
    float mrow0 = -1e30f, mrow1 = -1e30f, lrow0 = 0.f, lrow1 = 0.f;

    uint32_t aQ[4][4];            // Q fragments, loop-invariant

    const int nCh = S >> 6;
    for (int c = 0; c < nCh; c++) {
        cp_wait1();
        __syncthreads();
        if (c == 0) {             // hoisted Q fragment loads (once)
            #pragma unroll
            for (int ks = 0; ks < 4; ks++) {
                int row = wid * 16 + (lane & 15);
                int cc  = 2 * ks + (lane >> 4);
                ldsm4(aQ[ks], sQ + row * 128 + ((cc ^ (row & 7)) << 4));
            }
        }
        const uint32_t sb = sKV + (c % 3) * 16384;

        // ---- scores ----
        float sc[8][4];
        #pragma unroll
        for (int i = 0; i < 8; i++)
            #pragma unroll
            for (int j = 0; j < 4; j++) sc[i][j] = 0.f;
        #pragma unroll
        for (int ks = 0; ks < 4; ks++) {
            #pragma unroll
            for (int ntp = 0; ntp < 4; ntp++) {
                int nrow = ntp * 16 + (lane & 7) + ((lane & 16) ? 8 : 0);
                int cc   = 2 * ks + ((lane >> 3) & 1);
                uint32_t bq[4];
                ldsm4(bq, sb + nrow * 128 + ((cc ^ (nrow & 7)) << 4));
                mma_fp16(sc[ntp * 2 + 0], aQ[ks], bq);
                mma_fp16(sc[ntp * 2 + 1], aQ[ks], bq + 2);
            }
        }

        // ---- online softmax (scores already scaled via Q) ----
        float mx0 = -1e30f, mx1 = -1e30f;
        #pragma unroll
        for (int nt = 0; nt < 8; nt++) {
            mx0 = fmaxf(mx0, fmaxf(sc[nt][0], sc[nt][1]));
            mx1 = fmaxf(mx1, fmaxf(sc[nt][2], sc[nt][3]));
        }
        mx0 = fmaxf(mx0, __shfl_xor_sync(~0u, mx0, 1));
        mx0 = fmaxf(mx0, __shfl_xor_sync(~0u, mx0, 2));
        mx1 = fmaxf(mx1, __shfl_xor_sync(~0u, mx1, 1));
        mx1 = fmaxf(mx1, __shfl_xor_sync(~0u, mx1, 2));
        float mn0 = fmaxf(mrow0, mx0), mn1 = fmaxf(mrow1, mx1);
        float cf0 = __expf(mrow0 - mn0), cf1 = __expf(mrow1 - mn1);
        mrow0 = mn0; mrow1 = mn1;
        float sum0 = 0.f, sum1 = 0.f;
        #pragma unroll
        for (int nt = 0; nt < 8; nt++) {
            sc[nt][0] = __expf(sc[nt][0] - mn0); sum0 += sc[nt][0];
            sc[nt][1] = __expf(sc[nt][1] - mn0); sum0 += sc[nt][1];
            sc[nt][2] = __expf(sc[nt][2] - mn1); sum1 += sc[nt][2];
            sc[nt][3] = __expf(sc[nt][3] - mn1); sum1 += sc[nt][3];
        }
        sum0 += __shfl_xor_sync(~0u, sum0, 1);
        sum0 += __shfl_xor_sync(~0u, sum0, 2);
        sum1 += __shfl_xor_sync(~0u, sum1, 1);
        sum1 += __shfl_xor_sync(~0u, sum1, 2);
        lrow0 = lrow0 * cf0 + sum0;
        lrow1 = lrow1 * cf1 + sum1;
        #pragma unroll
        for (int nt = 0; nt < 8; nt++) {
            out[nt][0] *= cf0; out[nt][1] *= cf0;
            out[nt][2] *= cf1; out[nt][3] *= cf1;
        }

        // ---- PV ----
        #pragma unroll
        for (int t = 0; t < 4; t++) {
            uint32_t aP[4];
            aP[0] = h2u(__floats2half2_rn(sc[2*t][0],   sc[2*t][1]));
            aP[1] = h2u(__floats2half2_rn(sc[2*t][2],   sc[2*t][3]));
            aP[2] = h2u(__floats2half2_rn(sc[2*t+1][0], sc[2*t+1][1]));
            aP[3] = h2u(__floats2half2_rn(sc[2*t+1][2], sc[2*t+1][3]));
            #pragma unroll
            for (int ntp = 0; ntp < 4; ntp++) {
                int row = 16 * t + (lane & 7) + ((lane & 8) ? 8 : 0);
                int cc  = 2 * ntp + (lane >> 4);
                uint32_t bv[4];
                ldsm4t(bv, sb + 8192 + row * 128 + ((cc ^ (row & 7)) << 4));
                mma_fp16(out[ntp * 2 + 0], aP, bv);
                mma_fp16(out[ntp * 2 + 1], aP, bv + 2);
            }
        }
        if (c + 2 < nCh) issue_kv(c + 2);
        cp_commit();
    }

    float inv0 = 1.f / lrow0, inv1 = 1.f / lrow1;
    int trow0 = t0 + wid * 16 + (lane >> 2);
    size_t gr0 = (size_t)(trow0 * BATCH + b) * D_MODEL;
    size_t gr1 = (size_t)((trow0 + 8) * BATCH + b) * D_MODEL;
    #pragma unroll
    for (int nt = 0; nt < 8; nt++) {
        int col = hcol + nt * 8 + (lane & 3) * 2;
        *(uint32_t*)(O + gr0 + col) =
            h2u(__floats2half2_rn(out[nt][0] * inv0, out[nt][1] * inv0));
        *(uint32_t*)(O + gr1 + col) =
            h2u(__floats2half2_rn(out[nt][2] * inv1, out[nt][3] * inv1));
    }
}

// ---------------- fp32 -> fp16 convert ---------------------------------------
__global__ __launch_bounds__(256) void cvt_kernel(
    const float4* __restrict__ src, uint2* __restrict__ dst)
{
    size_t i = (size_t)blockIdx.x * 256 + threadIdx.x;
    float4 v = src[i];
    dst[i] = make_uint2(h2u(__floats2half2_rn(v.x, v.y)),
                        h2u(__floats2half2_rn(v.z, v.w)));
}

// ---------------- LayerNorm -> fp16 ------------------------------------------
__global__ __launch_bounds__(256) void ln_kernel(
    const float* __restrict__ x, const float* __restrict__ g,
    const float* __restrict__ b, __half* __restrict__ y)
{
    int row = blockIdx.x;
    const float4* xr = (const float4*)(x + (size_t)row * D_MODEL);
    int tid = threadIdx.x;
    float4 v = xr[tid];
    float s  = v.x + v.y + v.z + v.w;
    float ss = v.x*v.x + v.y*v.y + v.z*v.z + v.w*v.w;
    #pragma unroll
    for (int o = 16; o; o >>= 1) {
        s  += __shfl_xor_sync(~0u, s,  o);
        ss += __shfl_xor_sync(~0u, ss, o);
    }
    __shared__ float smS[8], smSS[8];
    int w = tid >> 5;
    if ((tid & 31) == 0) { smS[w] = s; smSS[w] = ss; }
    __syncthreads();
    if (tid < 32) {
        s  = (tid < 8) ? smS[tid]  : 0.f;
        ss = (tid < 8) ? smSS[tid] : 0.f;
        #pragma unroll
        for (int o = 4; o; o >>= 1) {
            s  += __shfl_xor_sync(~0u, s,  o);
            ss += __shfl_xor_sync(~0u, ss, o);
        }
        if (tid == 0) { smS[0] = s; smSS[0] = ss; }
    }
    __syncthreads();
    float mean = smS[0] * (1.f / D_MODEL);
    float var  = smSS[0] * (1.f / D_MODEL) - mean * mean;
    float rstd = rsqrtf(var + 1e-5f);
    float4 gv = ((const float4*)g)[tid];
    float4 bv = ((const float4*)b)[tid];
    float4 o;
    o.x = (v.x - mean) * rstd * gv.x + bv.x;
    o.y = (v.y - mean) * rstd * gv.y + bv.y;
    o.z = (v.z - mean) * rstd * gv.z + bv.z;
    o.w = (v.w - mean) * rstd * gv.w + bv.w;
    ((uint2*)(y + (size_t)row * D_MODEL))[tid] =
        make_uint2(h2u(__floats2half2_rn(o.x, o.y)),
                   h2u(__floats2half2_rn(o.z, o.w)));
}

// ---------------- orchestration ---------------------------------------------
extern "C" void kernel_launch(void* const* d_in, const int* in_sizes, int n_in,
                              void* d_out, int out_size)
{
    const float* x        = (const float*)d_in[0];
    const float* hid      = (const float*)d_in[1];
    const float* ln1_g    = (const float*)d_in[2];
    const float* ln1_b    = (const float*)d_in[3];
    const float* sa_in_w  = (const float*)d_in[4];
    const float* sa_in_b  = (const float*)d_in[5];
    const float* sa_out_w = (const float*)d_in[6];
    const float* sa_out_b = (const float*)d_in[7];
    const float* ln2_g    = (const float*)d_in[8];
    const float* ln2_b    = (const float*)d_in[9];
    const float* ca_in_w  = (const float*)d_in[10];
    const float* ca_in_b  = (const float*)d_in[11];
    const float* ca_out_w = (const float*)d_in[12];
    const float* ca_out_b = (const float*)d_in[13];
    const float* ln3_g    = (const float*)d_in[14];
    const float* ln3_b    = (const float*)d_in[15];
    const float* fc_w     = (const float*)d_in[16];
    const float* fc_b     = (const float*)d_in[17];
    const float* proj_w   = (const float*)d_in[18];
    const float* proj_b   = (const float*)d_in[19];
    float* out = (float*)d_out;

    __half *w, *hidc, *h, *qkv, *kv, *ctx, *ffn;
    cudaGetSymbolAddress((void**)&w,    g_w);
    cudaGetSymbolAddress((void**)&hidc, g_hid);
    cudaGetSymbolAddress((void**)&h,    g_h);
    cudaGetSymbolAddress((void**)&qkv,  g_qkv);
    cudaGetSymbolAddress((void**)&kv,   g_kv);
    cudaGetSymbolAddress((void**)&ctx,  g_ctx);
    cudaGetSymbolAddress((void**)&ffn,  g_ffn);

    const int SMG = 98304;
    cudaFuncSetAttribute(gemm_fp16,
                         cudaFuncAttributeMaxDynamicSharedMemorySize, SMG);
    cudaFuncSetAttribute(flash_kernel,
                         cudaFuncAttributeMaxDynamicSharedMemorySize, FLASH_SMEM);

    // ---- side stream + events ----
    cudaStream_t sb;
    cudaStreamCreateWithFlags(&sb, cudaStreamNonBlocking);
    cudaEvent_t e0, eSAIN, eSAOUT, eCAIN, eKV, eCAOUT, eFC, ePROJ;
    cudaEventCreateWithFlags(&e0,     cudaEventDisableTiming);
    cudaEventCreateWithFlags(&eSAIN,  cudaEventDisableTiming);
    cudaEventCreateWithFlags(&eSAOUT, cudaEventDisableTiming);
    cudaEventCreateWithFlags(&eCAIN,  cudaEventDisableTiming);
    cudaEventCreateWithFlags(&eKV,    cudaEventDisableTiming);
    cudaEventCreateWithFlags(&eCAOUT, cudaEventDisableTiming);
    cudaEventCreateWithFlags(&eFC,    cudaEventDisableTiming);
    cudaEventCreateWithFlags(&ePROJ,  cudaEventDisableTiming);

    cudaEventRecord(e0, 0);
    cudaStreamWaitEvent(sb, e0, 0);

    // ---- side stream: weight cvts + cross-KV GEMM ----
    cvt_kernel<<<3072, 256, 0, sb>>>((const float4*)sa_in_w,
                                     (uint2*)(w + WS_SA_IN));
    cudaEventRecord(eSAIN, sb);
    cvt_kernel<<<1024, 256, 0, sb>>>((const float4*)sa_out_w,
                                     (uint2*)(w + WS_SA_OUT));
    cudaEventRecord(eSAOUT, sb);
    cvt_kernel<<<3072, 256, 0, sb>>>((const float4*)ca_in_w,
                                     (uint2*)(w + WS_CA_IN));
    cudaEventRecord(eCAIN, sb);
    cvt_kernel<<<16384, 256, 0, sb>>>((const float4*)hid, (uint2*)hidc);
    gemm_fp16<<<dim3(16, 128), 256, SMG, sb>>>(
        hidc, 1024, w + WS_CA_IN + 1048576, 1024,
        ca_in_b + 1024, nullptr, nullptr, kv, 2048, 1024, 0, 0);
    cudaEventRecord(eKV, sb);
    cvt_kernel<<<1024, 256, 0, sb>>>((const float4*)ca_out_w,
                                     (uint2*)(w + WS_CA_OUT));
    cudaEventRecord(eCAOUT, sb);
    cvt_kernel<<<4096, 256, 0, sb>>>((const float4*)fc_w,
                                     (uint2*)(w + WS_FC));
    cudaEventRecord(eFC, sb);
    cvt_kernel<<<4096, 256, 0, sb>>>((const float4*)proj_w,
                                     (uint2*)(w + WS_PROJ));
    cudaEventRecord(ePROJ, sb);

    // ---- main stream: self attention ----
    ln_kernel<<<MQ, 256>>>(x, ln1_g, ln1_b, h);
    cudaStreamWaitEvent(0, eSAIN, 0);
    gemm_fp16<<<dim3(24, 64), 256, SMG>>>(
        h, 1024, w + WS_SA_IN, 1024,
        sa_in_b, nullptr, nullptr, qkv, 3072, 1024, 0, 1024);
    flash_kernel<<<dim3(1, 4, 256), 256, FLASH_SMEM>>>(
        qkv, 3072, qkv + 1024, 3072, qkv + 2048, 3072, ctx, T_LEN);
    cudaStreamWaitEvent(0, eSAOUT, 0);
    gemm_fp16<<<dim3(8, 64), 256, SMG>>>(
        ctx, 1024, w + WS_SA_OUT, 1024,
        sa_out_b, x, out, nullptr, 1024, 1024, 0, 0);

    // ---- main stream: cross attention ----
    ln_kernel<<<MQ, 256>>>(out, ln2_g, ln2_b, h);
    cudaStreamWaitEvent(0, eCAIN, 0);
    gemm_fp16<<<dim3(8, 64), 256, SMG>>>(
        h, 1024, w + WS_CA_IN, 1024,
        ca_in_b, nullptr, nullptr, qkv, 1024, 1024, 0, 1024);
    cudaStreamWaitEvent(0, eKV, 0);
    flash_kernel<<<dim3(1, 4, 256), 256, FLASH_SMEM>>>(
        qkv, 1024, kv, 2048, kv + 1024, 2048, ctx, S_LEN);
    cudaStreamWaitEvent(0, eCAOUT, 0);
    gemm_fp16<<<dim3(8, 64), 256, SMG>>>(
        ctx, 1024, w + WS_CA_OUT, 1024,
        ca_out_b, out, out, nullptr, 1024, 1024, 0, 0);

    // ---- main stream: MLP ----
    ln_kernel<<<MQ, 256>>>(out, ln3_g, ln3_b, h);
    cudaStreamWaitEvent(0, eFC, 0);
    gemm_fp16<<<dim3(32, 64), 256, SMG>>>(
        h, 1024, w + WS_FC, 1024,
        fc_b, nullptr, nullptr, ffn, 4096, 1024, 1, 0);
    cudaStreamWaitEvent(0, ePROJ, 0);
    gemm_fp16<<<dim3(8, 64), 256, SMG>>>(
        ffn, 4096, w + WS_PROJ, 4096,
        proj_b, out, out, nullptr, 1024, 4096, 0, 0);
}